// round 1
// baseline (speedup 1.0000x reference)
#include <cuda_runtime.h>
#include <math.h>
#include <stdint.h>

// Problem constants (fixed shapes from reference)
#define D_MODEL 2048
#define T_SEQ   4096
#define NH      16
#define NKV     4
#define DH      128
#define DKV     512   // NKV * DH

// Scratch (device globals; no allocation allowed)
__device__ float g_Q[T_SEQ * D_MODEL];     // 32 MB
__device__ float g_K[T_SEQ * DKV];         // 8 MB
__device__ float g_V[T_SEQ * DKV];         // 8 MB
__device__ float g_Ctx[T_SEQ * D_MODEL];   // 32 MB
__device__ float g_cosT[T_SEQ * (DH/2)];   // 1 MB
__device__ float g_sinT[T_SEQ * (DH/2)];   // 1 MB

// ---------------------------------------------------------------------------
// Classic tiled SGEMM: C[M,N] = A[M,K] @ B[K,N], all row-major fp32.
// BM=BN=128, BK=8, 256 threads, 8x8 per-thread microtile, float4 I/O.
// Requires M%128==0, N%128==0, K%8==0.
// ---------------------------------------------------------------------------
__global__ __launch_bounds__(256) void sgemm128(
    const float* __restrict__ A, const float* __restrict__ B,
    float* __restrict__ C, int M, int N, int K)
{
    __shared__ float As[8][128];   // transposed A tile
    __shared__ float Bs[8][128];

    const int tid = threadIdx.x;
    const float* Ab = A + (size_t)blockIdx.y * 128 * K;
    const float* Bb = B + (size_t)blockIdx.x * 128;
    float* Cb = C + (size_t)blockIdx.y * 128 * N + (size_t)blockIdx.x * 128;

    const int tr = tid >> 4;          // 0..15
    const int tc = tid & 15;          // 0..15
    const int aRow = tid >> 1;        // 0..127
    const int aCol = (tid & 1) * 4;   // 0 or 4
    const int bRow = tid >> 5;        // 0..7
    const int bCol = (tid & 31) * 4;  // 0..124

    float acc[8][8];
    #pragma unroll
    for (int i = 0; i < 8; i++)
        #pragma unroll
        for (int j = 0; j < 8; j++) acc[i][j] = 0.f;

    for (int k0 = 0; k0 < K; k0 += 8) {
        float4 av = *(const float4*)(Ab + (size_t)aRow * K + k0 + aCol);
        As[aCol + 0][aRow] = av.x;
        As[aCol + 1][aRow] = av.y;
        As[aCol + 2][aRow] = av.z;
        As[aCol + 3][aRow] = av.w;
        *(float4*)(&Bs[bRow][bCol]) =
            *(const float4*)(Bb + (size_t)(k0 + bRow) * N + bCol);
        __syncthreads();

        #pragma unroll
        for (int k = 0; k < 8; k++) {
            float4 a0 = *(float4*)&As[k][tr * 8];
            float4 a1 = *(float4*)&As[k][tr * 8 + 4];
            float4 b0 = *(float4*)&Bs[k][tc * 8];
            float4 b1 = *(float4*)&Bs[k][tc * 8 + 4];
            float ra[8] = {a0.x, a0.y, a0.z, a0.w, a1.x, a1.y, a1.z, a1.w};
            float rb[8] = {b0.x, b0.y, b0.z, b0.w, b1.x, b1.y, b1.z, b1.w};
            #pragma unroll
            for (int i = 0; i < 8; i++)
                #pragma unroll
                for (int j = 0; j < 8; j++)
                    acc[i][j] += ra[i] * rb[j];
        }
        __syncthreads();
    }

    #pragma unroll
    for (int i = 0; i < 8; i++) {
        float* crow = Cb + (size_t)(tr * 8 + i) * N + tc * 8;
        *(float4*)(crow)     = make_float4(acc[i][0], acc[i][1], acc[i][2], acc[i][3]);
        *(float4*)(crow + 4) = make_float4(acc[i][4], acc[i][5], acc[i][6], acc[i][7]);
    }
}

// ---------------------------------------------------------------------------
// RoPE tables: cos/sin(t * omega_i), omega_i = 10000^(-2i/128), computed in
// double for accuracy (t up to 4095 amplifies omega rounding).
// ---------------------------------------------------------------------------
__global__ void rope_table()
{
    int idx = blockIdx.x * blockDim.x + threadIdx.x;
    if (idx >= T_SEQ * (DH / 2)) return;
    int t = idx >> 6;
    int i = idx & 63;
    double omega = exp(-((double)(2 * i) / (double)DH) * log(10000.0));
    double ang = (double)t * omega;
    g_cosT[idx] = (float)cos(ang);
    g_sinT[idx] = (float)sin(ang);
}

// Apply RoPE in place to a [T_SEQ, cols] buffer, cols multiple of DH.
__global__ void rope_apply(float* __restrict__ buf, int cols)
{
    int halfc = cols >> 1;
    int idx = blockIdx.x * blockDim.x + threadIdx.x;
    if (idx >= T_SEQ * halfc) return;
    int t = idx / halfc;
    int p = idx - t * halfc;
    int i = p & 63;                       // pair index within head
    int col = ((p >> 6) << 7) + (i << 1); // head*128 + 2*i
    float c = g_cosT[(t << 6) + i];
    float s = g_sinT[(t << 6) + i];
    float* r = buf + (size_t)t * cols + col;
    float a = r[0], b = r[1];
    r[0] = a * c - b * s;
    r[1] = a * s + b * c;
}

// ---------------------------------------------------------------------------
// Causal flash attention (fp32 SIMT). BQ=BK=64, d=128.
// Grid: (NH, T/64). 256 threads = 16x16; S microtile 4x4, O microtile 4x8.
// ---------------------------------------------------------------------------
#define BQ 64
#define BKV 64
#define KSTRIDE 132   // padded row stride for Q/K/V tiles (float4-aligned)
#define SSTRIDE 66    // padded row stride for the S/P tile

#define ATTN_SMEM_FLOATS (3 * BQ * KSTRIDE + BQ * SSTRIDE + 256 + 3 * 64)
#define ATTN_SMEM_BYTES  (ATTN_SMEM_FLOATS * 4)

__global__ __launch_bounds__(256) void attn_kernel()
{
    extern __shared__ float sm[];
    float* Qs    = sm;                          // 64*132
    float* Ks    = Qs + BQ * KSTRIDE;           // 64*132
    float* Vs    = Ks + BKV * KSTRIDE;          // 64*132
    float* Ss    = Vs + BKV * KSTRIDE;          // 64*66
    float* red   = Ss + BQ * SSTRIDE;           // 64*4 partials
    float* m_sh  = red + 256;                   // 64
    float* l_sh  = m_sh + 64;                   // 64
    float* al_sh = l_sh + 64;                   // 64

    const int h  = blockIdx.x;
    const int qb = (int)(gridDim.y - 1) - (int)blockIdx.y;  // heavy blocks first
    const int g  = h >> 2;                                   // kv head
    const int tid = threadIdx.x;
    const int ty = tid >> 4;   // 0..15
    const int tx = tid & 15;   // 0..15

    const float scale = 0.08838834764831845f;  // 1/sqrt(128)

    // Load Q tile (pre-scaled)
    for (int idx = tid; idx < BQ * DH; idx += 256) {
        int r = idx >> 7, c = idx & 127;
        Qs[r * KSTRIDE + c] =
            g_Q[(size_t)(qb * BQ + r) * D_MODEL + h * DH + c] * scale;
    }
    if (tid < 64) { m_sh[tid] = -INFINITY; l_sh[tid] = 0.f; }

    float o[4][8];
    #pragma unroll
    for (int i = 0; i < 4; i++)
        #pragma unroll
        for (int c = 0; c < 8; c++) o[i][c] = 0.f;

    for (int kb = 0; kb <= qb; kb++) {
        __syncthreads();  // previous iteration done with Ks/Vs/Ss
        for (int idx = tid; idx < BKV * DH; idx += 256) {
            int r = idx >> 7, c = idx & 127;
            size_t goff = (size_t)(kb * BKV + r) * DKV + g * DH + c;
            Ks[r * KSTRIDE + c] = g_K[goff];
            Vs[r * KSTRIDE + c] = g_V[goff];
        }
        __syncthreads();

        // S = Q K^T  (4x4 microtile)
        float s[4][4];
        #pragma unroll
        for (int i = 0; i < 4; i++)
            #pragma unroll
            for (int j = 0; j < 4; j++) s[i][j] = 0.f;

        #pragma unroll 4
        for (int k = 0; k < DH; k += 4) {
            float4 qa[4], kv[4];
            #pragma unroll
            for (int i = 0; i < 4; i++)
                qa[i] = *(float4*)&Qs[(ty * 4 + i) * KSTRIDE + k];
            #pragma unroll
            for (int j = 0; j < 4; j++)
                kv[j] = *(float4*)&Ks[(tx * 4 + j) * KSTRIDE + k];
            #pragma unroll
            for (int i = 0; i < 4; i++)
                #pragma unroll
                for (int j = 0; j < 4; j++) {
                    s[i][j] += qa[i].x * kv[j].x;
                    s[i][j] += qa[i].y * kv[j].y;
                    s[i][j] += qa[i].z * kv[j].z;
                    s[i][j] += qa[i].w * kv[j].w;
                }
        }

        if (kb == qb) {
            #pragma unroll
            for (int i = 0; i < 4; i++)
                #pragma unroll
                for (int j = 0; j < 4; j++)
                    if (tx * 4 + j > ty * 4 + i) s[i][j] = -INFINITY;
        }

        #pragma unroll
        for (int i = 0; i < 4; i++)
            #pragma unroll
            for (int j = 0; j < 4; j++)
                Ss[(ty * 4 + i) * SSTRIDE + tx * 4 + j] = s[i][j];
        __syncthreads();

        // row max (partial over 16-col segments)
        {
            int r = tid >> 2, seg = tid & 3;
            float mx = -INFINITY;
            int base = r * SSTRIDE + seg * 16;
            #pragma unroll
            for (int j = 0; j < 16; j++) mx = fmaxf(mx, Ss[base + j]);
            red[r * 4 + seg] = mx;
        }
        __syncthreads();
        if (tid < 64) {
            float mo = m_sh[tid];
            float mn = fmaxf(fmaxf(red[tid * 4], red[tid * 4 + 1]),
                             fmaxf(red[tid * 4 + 2], red[tid * 4 + 3]));
            mn = fmaxf(mo, mn);
            m_sh[tid] = mn;
            al_sh[tid] = expf(mo - mn);
        }
        __syncthreads();
        // exponentiate + partial row sums
        {
            int r = tid >> 2, seg = tid & 3;
            float mn = m_sh[r];
            float sum = 0.f;
            int base = r * SSTRIDE + seg * 16;
            #pragma unroll
            for (int j = 0; j < 16; j++) {
                float p = expf(Ss[base + j] - mn);
                Ss[base + j] = p;
                sum += p;
            }
            red[r * 4 + seg] = sum;
        }
        __syncthreads();
        if (tid < 64) {
            l_sh[tid] = l_sh[tid] * al_sh[tid] +
                        (red[tid * 4] + red[tid * 4 + 1] +
                         red[tid * 4 + 2] + red[tid * 4 + 3]);
        }

        // rescale O and accumulate P @ V
        float a_[4];
        #pragma unroll
        for (int i = 0; i < 4; i++) a_[i] = al_sh[ty * 4 + i];
        #pragma unroll
        for (int i = 0; i < 4; i++)
            #pragma unroll
            for (int c = 0; c < 8; c++) o[i][c] *= a_[i];

        #pragma unroll 4
        for (int j = 0; j < BKV; j++) {
            float4 v0 = *(float4*)&Vs[j * KSTRIDE + tx * 8];
            float4 v1 = *(float4*)&Vs[j * KSTRIDE + tx * 8 + 4];
            #pragma unroll
            for (int i = 0; i < 4; i++) {
                float p = Ss[(ty * 4 + i) * SSTRIDE + j];
                o[i][0] += p * v0.x; o[i][1] += p * v0.y;
                o[i][2] += p * v0.z; o[i][3] += p * v0.w;
                o[i][4] += p * v1.x; o[i][5] += p * v1.y;
                o[i][6] += p * v1.z; o[i][7] += p * v1.w;
            }
        }
    }
    __syncthreads();  // l_sh final

    #pragma unroll
    for (int i = 0; i < 4; i++) {
        float inv = 1.f / l_sh[ty * 4 + i];
        int t = qb * BQ + ty * 4 + i;
        float* dst = &g_Ctx[(size_t)t * D_MODEL + h * DH + tx * 8];
        *(float4*)(dst) = make_float4(o[i][0] * inv, o[i][1] * inv,
                                      o[i][2] * inv, o[i][3] * inv);
        *(float4*)(dst + 4) = make_float4(o[i][4] * inv, o[i][5] * inv,
                                          o[i][6] * inv, o[i][7] * inv);
    }
}

// ---------------------------------------------------------------------------
extern "C" void kernel_launch(void* const* d_in, const int* in_sizes, int n_in,
                              void* d_out, int out_size)
{
    const float* x  = (const float*)d_in[0];
    const float* WQ = (const float*)d_in[1];
    const float* WK = (const float*)d_in[2];
    const float* WV = (const float*)d_in[3];
    const float* WO = (const float*)d_in[4];
    float* out = (float*)d_out;

    float *Qp, *Kp, *Vp, *Cp;
    cudaGetSymbolAddress((void**)&Qp, g_Q);
    cudaGetSymbolAddress((void**)&Kp, g_K);
    cudaGetSymbolAddress((void**)&Vp, g_V);
    cudaGetSymbolAddress((void**)&Cp, g_Ctx);

    // Q/K/V projections
    sgemm128<<<dim3(D_MODEL / 128, T_SEQ / 128), 256>>>(x, WQ, Qp, T_SEQ, D_MODEL, D_MODEL);
    sgemm128<<<dim3(DKV / 128,     T_SEQ / 128), 256>>>(x, WK, Kp, T_SEQ, DKV,     D_MODEL);
    sgemm128<<<dim3(DKV / 128,     T_SEQ / 128), 256>>>(x, WV, Vp, T_SEQ, DKV,     D_MODEL);

    // RoPE
    {
        int n = T_SEQ * (DH / 2);
        rope_table<<<(n + 255) / 256, 256>>>();
    }
    {
        int n = T_SEQ * (D_MODEL / 2);
        rope_apply<<<(n + 255) / 256, 256>>>(Qp, D_MODEL);
    }
    {
        int n = T_SEQ * (DKV / 2);
        rope_apply<<<(n + 255) / 256, 256>>>(Kp, DKV);
    }

    // Attention
    cudaFuncSetAttribute(attn_kernel,
                         cudaFuncAttributeMaxDynamicSharedMemorySize,
                         ATTN_SMEM_BYTES);
    attn_kernel<<<dim3(NH, T_SEQ / BQ), 256, ATTN_SMEM_BYTES>>>();

    // Output projection -> d_out
    sgemm128<<<dim3(D_MODEL / 128, T_SEQ / 128), 256>>>(Cp, WO, out, T_SEQ, D_MODEL, D_MODEL);
}

// round 2
// speedup vs baseline: 3.4181x; 3.4181x over previous
#include <cuda_runtime.h>
#include <math.h>
#include <stdint.h>

// Problem constants (fixed shapes from reference)
#define D_MODEL 2048
#define T_SEQ   4096
#define NH      16
#define NKV     4
#define DH      128
#define DKV     512   // NKV * DH

// Scratch (device globals; no allocation allowed)
__device__ float g_Q[T_SEQ * D_MODEL];     // 32 MB
__device__ float g_K[T_SEQ * DKV];         // 8 MB
__device__ float g_V[T_SEQ * DKV];         // 8 MB
__device__ float g_Ctx[T_SEQ * D_MODEL];   // 32 MB
__device__ float g_cosT[T_SEQ * (DH/2)];   // 1 MB
__device__ float g_sinT[T_SEQ * (DH/2)];   // 1 MB

// ---------------------------------------------------------------------------
// tf32 helpers
// ---------------------------------------------------------------------------
__device__ __forceinline__ uint32_t f2tf(float x) {
    uint32_t r;
    asm("cvt.rna.tf32.f32 %0, %1;" : "=r"(r) : "f"(x));
    return r;
}
__device__ __forceinline__ float f2tf_f(float x) {
    return __uint_as_float(f2tf(x));
}
// D += A(16x8) * B(8x8), tf32 inputs (as raw b32), fp32 accum
__device__ __forceinline__ void mma_tf32(float* d, const uint32_t* a, const uint32_t* b) {
    asm volatile(
        "mma.sync.aligned.m16n8k8.row.col.f32.tf32.tf32.f32 "
        "{%0,%1,%2,%3}, {%4,%5,%6,%7}, {%8,%9}, {%0,%1,%2,%3};"
        : "+f"(d[0]), "+f"(d[1]), "+f"(d[2]), "+f"(d[3])
        : "r"(a[0]), "r"(a[1]), "r"(a[2]), "r"(a[3]), "r"(b[0]), "r"(b[1]));
}
__device__ __forceinline__ uint32_t fu(float x) { return __float_as_uint(x); }

// ---------------------------------------------------------------------------
// tf32 GEMM: C[M,N] = A[M,K] @ B[K,N], row-major fp32 in/out.
// Block tile 128x128, K-chunk 32, 256 threads (8 warps as 4x2 of 32x64 tiles).
// Double-buffered smem, register prefetch.
// Requires M%128==0, N%128==0, K%32==0.
// ---------------------------------------------------------------------------
#define GA_STRIDE 136   // As transposed [32][128+8]; bank = 8*tig+g (unique)
#define GB_STRIDE 136   // Bs [32][128+8];          bank = 8*tig+g (unique)
#define GEMM_SMEM_FLOATS (2 * 32 * GA_STRIDE + 2 * 32 * GB_STRIDE)
#define GEMM_SMEM_BYTES  (GEMM_SMEM_FLOATS * 4)

__global__ __launch_bounds__(256) void gemm_tf32(
    const float* __restrict__ A, const float* __restrict__ B,
    float* __restrict__ C, int M, int N, int K)
{
    extern __shared__ float sm[];
    float* As[2] = { sm, sm + 32 * GA_STRIDE };
    float* Bs[2] = { sm + 2 * 32 * GA_STRIDE, sm + 2 * 32 * GA_STRIDE + 32 * GB_STRIDE };

    const int tid  = threadIdx.x;
    const int lane = tid & 31;
    const int w    = tid >> 5;
    const int wr   = w >> 1;      // 0..3 -> rows wr*32
    const int wc   = w & 1;       // 0..1 -> cols wc*64
    const int g    = lane >> 2;   // 0..7
    const int tig  = lane & 3;    // 0..3

    const int bm = blockIdx.y, bn = blockIdx.x;

    // A loading: thread covers row (tid>>1), k = (tid&1)*16 .. +15
    const int aRow = tid >> 1;
    const int aK0  = (tid & 1) * 16;
    const float* Ap = A + (size_t)(bm * 128 + aRow) * K + aK0;
    // B loading: thread covers row (tid>>3), n = (tid&7)*16 .. +15
    const int bRow = tid >> 3;
    const int bN0  = (tid & 7) * 16;
    const float* Bp = B + (size_t)bRow * N + bn * 128 + bN0;

    float acc[2][8][4];
    #pragma unroll
    for (int mt = 0; mt < 2; mt++)
        #pragma unroll
        for (int nf = 0; nf < 8; nf++)
            #pragma unroll
            for (int i = 0; i < 4; i++) acc[mt][nf][i] = 0.f;

    float4 pa[4], pb[4];
    // preload chunk 0
    #pragma unroll
    for (int q = 0; q < 4; q++) {
        pa[q] = *(const float4*)(Ap + 4 * q);
        pb[q] = *(const float4*)(Bp + 4 * q);
    }
    // store chunk 0 -> buf 0
    #pragma unroll
    for (int q = 0; q < 4; q++) {
        As[0][(aK0 + 4 * q + 0) * GA_STRIDE + aRow] = f2tf_f(pa[q].x);
        As[0][(aK0 + 4 * q + 1) * GA_STRIDE + aRow] = f2tf_f(pa[q].y);
        As[0][(aK0 + 4 * q + 2) * GA_STRIDE + aRow] = f2tf_f(pa[q].z);
        As[0][(aK0 + 4 * q + 3) * GA_STRIDE + aRow] = f2tf_f(pa[q].w);
        float4 t = make_float4(f2tf_f(pb[q].x), f2tf_f(pb[q].y),
                               f2tf_f(pb[q].z), f2tf_f(pb[q].w));
        *(float4*)&Bs[0][bRow * GB_STRIDE + bN0 + 4 * q] = t;
    }
    __syncthreads();

    const int nchunks = K / 32;
    int buf = 0;
    for (int c = 0; c < nchunks; c++) {
        if (c + 1 < nchunks) {
            const float* Ap2 = Ap + (c + 1) * 32;
            const float* Bp2 = Bp + (size_t)(c + 1) * 32 * N;
            #pragma unroll
            for (int q = 0; q < 4; q++) {
                pa[q] = *(const float4*)(Ap2 + 4 * q);
                pb[q] = *(const float4*)(Bp2 + 4 * q);
            }
        }
        // compute on buf
        float* Asb = As[buf];
        float* Bsb = Bs[buf];
        #pragma unroll
        for (int ks = 0; ks < 4; ks++) {
            uint32_t af[2][4], bf[8][2];
            #pragma unroll
            for (int mt = 0; mt < 2; mt++) {
                int m0 = wr * 32 + mt * 16 + g;
                af[mt][0] = fu(Asb[(ks * 8 + tig) * GA_STRIDE + m0]);
                af[mt][1] = fu(Asb[(ks * 8 + tig) * GA_STRIDE + m0 + 8]);
                af[mt][2] = fu(Asb[(ks * 8 + tig + 4) * GA_STRIDE + m0]);
                af[mt][3] = fu(Asb[(ks * 8 + tig + 4) * GA_STRIDE + m0 + 8]);
            }
            #pragma unroll
            for (int nf = 0; nf < 8; nf++) {
                int n0 = wc * 64 + nf * 8 + g;
                bf[nf][0] = fu(Bsb[(ks * 8 + tig) * GB_STRIDE + n0]);
                bf[nf][1] = fu(Bsb[(ks * 8 + tig + 4) * GB_STRIDE + n0]);
            }
            #pragma unroll
            for (int mt = 0; mt < 2; mt++)
                #pragma unroll
                for (int nf = 0; nf < 8; nf++)
                    mma_tf32(acc[mt][nf], af[mt], bf[nf]);
        }
        if (c + 1 < nchunks) {
            int nb = buf ^ 1;
            #pragma unroll
            for (int q = 0; q < 4; q++) {
                As[nb][(aK0 + 4 * q + 0) * GA_STRIDE + aRow] = f2tf_f(pa[q].x);
                As[nb][(aK0 + 4 * q + 1) * GA_STRIDE + aRow] = f2tf_f(pa[q].y);
                As[nb][(aK0 + 4 * q + 2) * GA_STRIDE + aRow] = f2tf_f(pa[q].z);
                As[nb][(aK0 + 4 * q + 3) * GA_STRIDE + aRow] = f2tf_f(pa[q].w);
                float4 t = make_float4(f2tf_f(pb[q].x), f2tf_f(pb[q].y),
                                       f2tf_f(pb[q].z), f2tf_f(pb[q].w));
                *(float4*)&Bs[nb][bRow * GB_STRIDE + bN0 + 4 * q] = t;
            }
            __syncthreads();
            buf = nb;
        }
    }

    // epilogue
    #pragma unroll
    for (int mt = 0; mt < 2; mt++) {
        int row0 = bm * 128 + wr * 32 + mt * 16 + g;
        #pragma unroll
        for (int nf = 0; nf < 8; nf++) {
            int col = bn * 128 + wc * 64 + nf * 8 + 2 * tig;
            *(float2*)&C[(size_t)row0 * N + col] =
                make_float2(acc[mt][nf][0], acc[mt][nf][1]);
            *(float2*)&C[(size_t)(row0 + 8) * N + col] =
                make_float2(acc[mt][nf][2], acc[mt][nf][3]);
        }
    }
}

// ---------------------------------------------------------------------------
// RoPE tables (double precision on host-side math not allowed; do it on GPU)
// ---------------------------------------------------------------------------
__global__ void rope_table()
{
    int idx = blockIdx.x * blockDim.x + threadIdx.x;
    if (idx >= T_SEQ * (DH / 2)) return;
    int t = idx >> 6;
    int i = idx & 63;
    double omega = exp(-((double)(2 * i) / (double)DH) * log(10000.0));
    double ang = (double)t * omega;
    g_cosT[idx] = (float)cos(ang);
    g_sinT[idx] = (float)sin(ang);
}

__global__ void rope_apply(float* __restrict__ buf, int cols)
{
    int halfc = cols >> 1;
    int idx = blockIdx.x * blockDim.x + threadIdx.x;
    if (idx >= T_SEQ * halfc) return;
    int t = idx / halfc;
    int p = idx - t * halfc;
    int i = p & 63;
    int col = ((p >> 6) << 7) + (i << 1);
    float c = g_cosT[(t << 6) + i];
    float s = g_sinT[(t << 6) + i];
    float* r = buf + (size_t)t * cols + col;
    float a = r[0], b = r[1];
    r[0] = a * c - b * s;
    r[1] = a * s + b * c;
}

// ---------------------------------------------------------------------------
// Causal flash attention, tf32 tensor cores. BQ=128, BKV=64, d=128.
// Grid: (NH, T/128). 256 threads = 8 warps.
//   S phase: warp tile 32x32 (wr=w>>1 rows, wc=w&1 cols)
//   PV phase: warp tile 32x64 (same rows, wc cols of 64)
// ---------------------------------------------------------------------------
#define BQ  128
#define BKV 64
#define QSTR 132   // Qs/Ks row stride: frag bank = 4g+tig (unique)
#define VSTR 136   // Vs row stride:    frag bank = 8tig+g (unique)
#define SSTR 68    // Ss row stride:    frag bank = 4g+tig (unique)

#define ATTN_SMEM_FLOATS (BQ*QSTR + BKV*QSTR + BKV*VSTR + BQ*SSTR + BQ*4 + 3*BQ)
#define ATTN_SMEM_BYTES  (ATTN_SMEM_FLOATS * 4)

__global__ __launch_bounds__(256) void attn_kernel()
{
    extern __shared__ float sm[];
    float* Qs   = sm;                    // 128 x 132
    float* Ks   = Qs + BQ * QSTR;        // 64 x 132
    float* Vs   = Ks + BKV * QSTR;       // 64 x 136
    float* Ss   = Vs + BKV * VSTR;       // 128 x 68
    float* red  = Ss + BQ * SSTR;        // 128 x 4
    float* m_sh = red + BQ * 4;          // 128
    float* l_sh = m_sh + BQ;             // 128
    float* al_sh= l_sh + BQ;             // 128

    const int h   = blockIdx.x;
    const int qb  = (int)(gridDim.y - 1) - (int)blockIdx.y;  // heavy-first
    const int gkv = h >> 2;
    const int tid  = threadIdx.x;
    const int lane = tid & 31;
    const int w    = tid >> 5;
    const int wr   = w >> 1;     // 0..3
    const int wc   = w & 1;      // 0..1
    const int g    = lane >> 2;  // 0..7
    const int tig  = lane & 3;   // 0..3

    const float scale = 0.08838834764831845f;  // 1/sqrt(128)

    // Q tile (pre-scaled, tf32-rounded)
    for (int idx = tid; idx < BQ * 32; idx += 256) {
        int r = idx >> 5, c4 = (idx & 31) * 4;
        float4 v = *(const float4*)&g_Q[(size_t)(qb * BQ + r) * D_MODEL + h * DH + c4];
        float4 t = make_float4(f2tf_f(v.x * scale), f2tf_f(v.y * scale),
                               f2tf_f(v.z * scale), f2tf_f(v.w * scale));
        *(float4*)&Qs[r * QSTR + c4] = t;
    }
    if (tid < BQ) { m_sh[tid] = -INFINITY; l_sh[tid] = 0.f; }

    float o[2][8][4];
    #pragma unroll
    for (int mt = 0; mt < 2; mt++)
        #pragma unroll
        for (int nf = 0; nf < 8; nf++)
            #pragma unroll
            for (int i = 0; i < 4; i++) o[mt][nf][i] = 0.f;

    const int nkb = 2 * qb + 2;
    for (int kb = 0; kb < nkb; kb++) {
        __syncthreads();  // guard Ks/Vs/Ss reuse
        for (int idx = tid; idx < BKV * 32; idx += 256) {
            int r = idx >> 5, c4 = (idx & 31) * 4;
            size_t goff = (size_t)(kb * BKV + r) * DKV + gkv * DH + c4;
            float4 kv = *(const float4*)&g_K[goff];
            float4 vv = *(const float4*)&g_V[goff];
            *(float4*)&Ks[r * QSTR + c4] = make_float4(f2tf_f(kv.x), f2tf_f(kv.y),
                                                       f2tf_f(kv.z), f2tf_f(kv.w));
            *(float4*)&Vs[r * VSTR + c4] = make_float4(f2tf_f(vv.x), f2tf_f(vv.y),
                                                       f2tf_f(vv.z), f2tf_f(vv.w));
        }
        __syncthreads();

        // S = Q K^T via mma
        float s[2][4][4];
        #pragma unroll
        for (int mt = 0; mt < 2; mt++)
            #pragma unroll
            for (int nf = 0; nf < 4; nf++)
                #pragma unroll
                for (int i = 0; i < 4; i++) s[mt][nf][i] = 0.f;

        #pragma unroll
        for (int ks = 0; ks < 16; ks++) {
            uint32_t af[2][4], bf[4][2];
            #pragma unroll
            for (int mt = 0; mt < 2; mt++) {
                int r0 = wr * 32 + mt * 16 + g;
                af[mt][0] = fu(Qs[r0 * QSTR + ks * 8 + tig]);
                af[mt][1] = fu(Qs[(r0 + 8) * QSTR + ks * 8 + tig]);
                af[mt][2] = fu(Qs[r0 * QSTR + ks * 8 + tig + 4]);
                af[mt][3] = fu(Qs[(r0 + 8) * QSTR + ks * 8 + tig + 4]);
            }
            #pragma unroll
            for (int nf = 0; nf < 4; nf++) {
                int c0 = wc * 32 + nf * 8 + g;
                bf[nf][0] = fu(Ks[c0 * QSTR + ks * 8 + tig]);
                bf[nf][1] = fu(Ks[c0 * QSTR + ks * 8 + tig + 4]);
            }
            #pragma unroll
            for (int mt = 0; mt < 2; mt++)
                #pragma unroll
                for (int nf = 0; nf < 4; nf++)
                    mma_tf32(s[mt][nf], af[mt], bf[nf]);
        }

        // causal mask (register-level) on diagonal-overlapping kb
        if (kb >= 2 * qb) {
            #pragma unroll
            for (int mt = 0; mt < 2; mt++) {
                int row0 = qb * BQ + wr * 32 + mt * 16 + g;
                #pragma unroll
                for (int nf = 0; nf < 4; nf++) {
                    int col = kb * BKV + wc * 32 + nf * 8 + 2 * tig;
                    if (col > row0)     s[mt][nf][0] = -INFINITY;
                    if (col + 1 > row0) s[mt][nf][1] = -INFINITY;
                    if (col > row0 + 8)     s[mt][nf][2] = -INFINITY;
                    if (col + 1 > row0 + 8) s[mt][nf][3] = -INFINITY;
                }
            }
        }

        // write S to smem
        #pragma unroll
        for (int mt = 0; mt < 2; mt++) {
            int r0 = wr * 32 + mt * 16 + g;
            #pragma unroll
            for (int nf = 0; nf < 4; nf++) {
                int c0 = wc * 32 + nf * 8 + 2 * tig;
                *(float2*)&Ss[r0 * SSTR + c0] = make_float2(s[mt][nf][0], s[mt][nf][1]);
                *(float2*)&Ss[(r0 + 8) * SSTR + c0] = make_float2(s[mt][nf][2], s[mt][nf][3]);
            }
        }
        __syncthreads();

        // row max partials (128 rows x 4 segs of 16)
        for (int u = tid; u < BQ * 4; u += 256) {
            int r = u >> 2, seg = u & 3;
            float mx = -INFINITY;
            int base = r * SSTR + seg * 16;
            #pragma unroll
            for (int j = 0; j < 16; j++) mx = fmaxf(mx, Ss[base + j]);
            red[u] = mx;
        }
        __syncthreads();
        if (tid < BQ) {
            float mo = m_sh[tid];
            float mn = fmaxf(fmaxf(red[tid * 4], red[tid * 4 + 1]),
                             fmaxf(red[tid * 4 + 2], red[tid * 4 + 3]));
            mn = fmaxf(mo, mn);
            m_sh[tid] = mn;
            al_sh[tid] = __expf(mo - mn);
        }
        __syncthreads();
        // exponentiate (tf32-rounded P) + partial sums
        for (int u = tid; u < BQ * 4; u += 256) {
            int r = u >> 2, seg = u & 3;
            float mn = m_sh[r];
            float sum = 0.f;
            int base = r * SSTR + seg * 16;
            #pragma unroll
            for (int j = 0; j < 16; j++) {
                float p = f2tf_f(__expf(Ss[base + j] - mn));
                Ss[base + j] = p;
                sum += p;
            }
            red[u] = sum;
        }
        __syncthreads();
        if (tid < BQ) {
            l_sh[tid] = l_sh[tid] * al_sh[tid] +
                        (red[tid * 4] + red[tid * 4 + 1] +
                         red[tid * 4 + 2] + red[tid * 4 + 3]);
        }

        // rescale O
        #pragma unroll
        for (int mt = 0; mt < 2; mt++) {
            int r0 = wr * 32 + mt * 16 + g;
            float a0 = al_sh[r0], a1 = al_sh[r0 + 8];
            #pragma unroll
            for (int nf = 0; nf < 8; nf++) {
                o[mt][nf][0] *= a0; o[mt][nf][1] *= a0;
                o[mt][nf][2] *= a1; o[mt][nf][3] *= a1;
            }
        }

        // O += P @ V via mma (k = 64 -> 8 k-steps)
        #pragma unroll
        for (int ks = 0; ks < 8; ks++) {
            uint32_t af[2][4], bf[8][2];
            #pragma unroll
            for (int mt = 0; mt < 2; mt++) {
                int r0 = wr * 32 + mt * 16 + g;
                af[mt][0] = fu(Ss[r0 * SSTR + ks * 8 + tig]);
                af[mt][1] = fu(Ss[(r0 + 8) * SSTR + ks * 8 + tig]);
                af[mt][2] = fu(Ss[r0 * SSTR + ks * 8 + tig + 4]);
                af[mt][3] = fu(Ss[(r0 + 8) * SSTR + ks * 8 + tig + 4]);
            }
            #pragma unroll
            for (int nf = 0; nf < 8; nf++) {
                int c0 = wc * 64 + nf * 8 + g;
                bf[nf][0] = fu(Vs[(ks * 8 + tig) * VSTR + c0]);
                bf[nf][1] = fu(Vs[(ks * 8 + tig + 4) * VSTR + c0]);
            }
            #pragma unroll
            for (int mt = 0; mt < 2; mt++)
                #pragma unroll
                for (int nf = 0; nf < 8; nf++)
                    mma_tf32(o[mt][nf], af[mt], bf[nf]);
        }
    }
    __syncthreads();  // l_sh final

    #pragma unroll
    for (int mt = 0; mt < 2; mt++) {
        int r0 = wr * 32 + mt * 16 + g;
        float inv0 = 1.f / l_sh[r0];
        float inv1 = 1.f / l_sh[r0 + 8];
        int trow0 = qb * BQ + r0;
        #pragma unroll
        for (int nf = 0; nf < 8; nf++) {
            int col = h * DH + wc * 64 + nf * 8 + 2 * tig;
            *(float2*)&g_Ctx[(size_t)trow0 * D_MODEL + col] =
                make_float2(o[mt][nf][0] * inv0, o[mt][nf][1] * inv0);
            *(float2*)&g_Ctx[(size_t)(trow0 + 8) * D_MODEL + col] =
                make_float2(o[mt][nf][2] * inv1, o[mt][nf][3] * inv1);
        }
    }
}

// ---------------------------------------------------------------------------
extern "C" void kernel_launch(void* const* d_in, const int* in_sizes, int n_in,
                              void* d_out, int out_size)
{
    const float* x  = (const float*)d_in[0];
    const float* WQ = (const float*)d_in[1];
    const float* WK = (const float*)d_in[2];
    const float* WV = (const float*)d_in[3];
    const float* WO = (const float*)d_in[4];
    float* out = (float*)d_out;

    float *Qp, *Kp, *Vp, *Cp;
    cudaGetSymbolAddress((void**)&Qp, g_Q);
    cudaGetSymbolAddress((void**)&Kp, g_K);
    cudaGetSymbolAddress((void**)&Vp, g_V);
    cudaGetSymbolAddress((void**)&Cp, g_Ctx);

    cudaFuncSetAttribute(gemm_tf32,
                         cudaFuncAttributeMaxDynamicSharedMemorySize,
                         GEMM_SMEM_BYTES);
    cudaFuncSetAttribute(attn_kernel,
                         cudaFuncAttributeMaxDynamicSharedMemorySize,
                         ATTN_SMEM_BYTES);

    // Q/K/V projections (tf32 tensor cores)
    gemm_tf32<<<dim3(D_MODEL / 128, T_SEQ / 128), 256, GEMM_SMEM_BYTES>>>(
        x, WQ, Qp, T_SEQ, D_MODEL, D_MODEL);
    gemm_tf32<<<dim3(DKV / 128, T_SEQ / 128), 256, GEMM_SMEM_BYTES>>>(
        x, WK, Kp, T_SEQ, DKV, D_MODEL);
    gemm_tf32<<<dim3(DKV / 128, T_SEQ / 128), 256, GEMM_SMEM_BYTES>>>(
        x, WV, Vp, T_SEQ, DKV, D_MODEL);

    // RoPE
    {
        int n = T_SEQ * (DH / 2);
        rope_table<<<(n + 255) / 256, 256>>>();
    }
    {
        int n = T_SEQ * (D_MODEL / 2);
        rope_apply<<<(n + 255) / 256, 256>>>(Qp, D_MODEL);
    }
    {
        int n = T_SEQ * (DKV / 2);
        rope_apply<<<(n + 255) / 256, 256>>>(Kp, DKV);
    }

    // Attention
    attn_kernel<<<dim3(NH, T_SEQ / BQ), 256, ATTN_SMEM_BYTES>>>();

    // Output projection -> d_out
    gemm_tf32<<<dim3(D_MODEL / 128, T_SEQ / 128), 256, GEMM_SMEM_BYTES>>>(
        Cp, WO, out, T_SEQ, D_MODEL, D_MODEL);
}

// round 5
// speedup vs baseline: 4.2691x; 1.2490x over previous
#include <cuda_runtime.h>
#include <math.h>
#include <stdint.h>

// Problem constants (fixed shapes from reference)
#define D_MODEL 2048
#define T_SEQ   4096
#define NH      16
#define NKV     4
#define DH      128
#define DKV     512   // NKV * DH

// Scratch (device globals; no allocation allowed)
__device__ float g_Q[T_SEQ * D_MODEL];       // 32 MB
__device__ float g_K[T_SEQ * DKV];           // 8 MB
__device__ float g_V[T_SEQ * DKV];           // 8 MB (tf32-rounded)
__device__ float g_Ctx[T_SEQ * D_MODEL];     // 32 MB (tf32-rounded)
__device__ float g_cosT[T_SEQ * (DH/2)];     // 1 MB
__device__ float g_sinT[T_SEQ * (DH/2)];     // 1 MB
__device__ float g_xT[T_SEQ * D_MODEL];      // 32 MB (tf32-rounded x)
__device__ float g_WTq[D_MODEL * D_MODEL];   // 16 MB  W^T (tf32-rounded)
__device__ float g_WTk[DKV * D_MODEL];       // 4 MB
__device__ float g_WTv[DKV * D_MODEL];       // 4 MB
__device__ float g_WTo[D_MODEL * D_MODEL];   // 16 MB

// ---------------------------------------------------------------------------
// helpers
// ---------------------------------------------------------------------------
__device__ __forceinline__ uint32_t f2tf(float x) {
    uint32_t r;
    asm("cvt.rna.tf32.f32 %0, %1;" : "=r"(r) : "f"(x));
    return r;
}
__device__ __forceinline__ float f2tf_f(float x) { return __uint_as_float(f2tf(x)); }
__device__ __forceinline__ uint32_t fu(float x) { return __float_as_uint(x); }

__device__ __forceinline__ uint32_t smem_to_u32(const void* p) {
    uint32_t a;
    asm("{ .reg .u64 t; cvta.to.shared.u64 t, %1; cvt.u32.u64 %0, t; }" : "=r"(a) : "l"(p));
    return a;
}

#define CP_ASYNC16(saddr, gptr) \
    asm volatile("cp.async.cg.shared.global [%0], [%1], 16;" \
                 :: "r"((uint32_t)(saddr)), "l"(gptr) : "memory")
#define CP_COMMIT  asm volatile("cp.async.commit_group;" ::: "memory")
#define CP_WAIT_0  asm volatile("cp.async.wait_group 0;" ::: "memory")
#define CP_WAIT_2  asm volatile("cp.async.wait_group 2;" ::: "memory")

#define LDSM_X4(d0, d1, d2, d3, addr) \
    asm volatile("ldmatrix.sync.aligned.m8n8.x4.shared.b16 {%0,%1,%2,%3}, [%4];" \
                 : "=r"(d0), "=r"(d1), "=r"(d2), "=r"(d3) : "r"((uint32_t)(addr)))

// D += A(16x8) * B(8x8), tf32 inputs (as raw b32), fp32 accum
__device__ __forceinline__ void mma_tf32(float* d, const uint32_t* a, const uint32_t* b) {
    asm volatile(
        "mma.sync.aligned.m16n8k8.row.col.f32.tf32.tf32.f32 "
        "{%0,%1,%2,%3}, {%4,%5,%6,%7}, {%8,%9}, {%0,%1,%2,%3};"
        : "+f"(d[0]), "+f"(d[1]), "+f"(d[2]), "+f"(d[3])
        : "r"(a[0]), "r"(a[1]), "r"(a[2]), "r"(a[3]), "r"(b[0]), "r"(b[1]));
}

// ---------------------------------------------------------------------------
// prep kernels
// ---------------------------------------------------------------------------
__global__ void round_x(const float* __restrict__ x)
{
    int i = (blockIdx.x * blockDim.x + threadIdx.x) * 4;
    float4 v = *(const float4*)(x + i);
    *(float4*)(g_xT + i) = make_float4(f2tf_f(v.x), f2tf_f(v.y), f2tf_f(v.z), f2tf_f(v.w));
}

// Transpose weights (and tf32-round): Wt[n][k] = rna(W[k][n]).
__global__ void transpose_w(const float* __restrict__ WQ, const float* __restrict__ WK,
                            const float* __restrict__ WV, const float* __restrict__ WO)
{
    __shared__ float t[32][33];
    const float* src; float* dst; int ncols;
    switch (blockIdx.z) {
        case 0: src = WQ; dst = g_WTq; ncols = D_MODEL; break;
        case 1: src = WK; dst = g_WTk; ncols = DKV; break;
        case 2: src = WV; dst = g_WTv; ncols = DKV; break;
        default: src = WO; dst = g_WTo; ncols = D_MODEL; break;
    }
    int k0 = blockIdx.x * 32, n0 = blockIdx.y * 32;
    if (n0 >= ncols) return;
    int tx = threadIdx.x, ty = threadIdx.y;  // 32 x 8
    #pragma unroll
    for (int i = 0; i < 4; i++)
        t[ty + 8 * i][tx] = src[(size_t)(k0 + ty + 8 * i) * ncols + n0 + tx];
    __syncthreads();
    #pragma unroll
    for (int i = 0; i < 4; i++)
        dst[(size_t)(n0 + ty + 8 * i) * D_MODEL + k0 + tx] = f2tf_f(t[tx][ty + 8 * i]);
}

__global__ void rope_table()
{
    int idx = blockIdx.x * blockDim.x + threadIdx.x;
    if (idx >= T_SEQ * (DH / 2)) return;
    int t = idx >> 6;
    int i = idx & 63;
    double omega = exp(-((double)(2 * i) / (double)DH) * log(10000.0));
    double ang = (double)t * omega;
    g_cosT[idx] = (float)cos(ang);
    g_sinT[idx] = (float)sin(ang);
}

// RoPE in place + scale + tf32-round outputs.
__global__ void rope_apply(float* __restrict__ buf, int cols, float scale)
{
    int halfc = cols >> 1;
    int idx = blockIdx.x * blockDim.x + threadIdx.x;
    if (idx >= T_SEQ * halfc) return;
    int t = idx / halfc;
    int p = idx - t * halfc;
    int i = p & 63;
    int col = ((p >> 6) << 7) + (i << 1);
    float c = g_cosT[(t << 6) + i];
    float s = g_sinT[(t << 6) + i];
    float* r = buf + (size_t)t * cols + col;
    float a = r[0], b = r[1];
    r[0] = f2tf_f((a * c - b * s) * scale);
    r[1] = f2tf_f((a * s + b * c) * scale);
}

// ---------------------------------------------------------------------------
// tf32 GEMM via mma.sync + cp.async + ldmatrix.
// C[M,N] = A[M,K] @ B[N,K]^T. A row-major [M,K] (tf32-pre-rounded),
// B K-major [N,K] (tf32-pre-rounded). Block tile 128x128, BK=32, 4 stages.
// 256 threads = 8 warps as 4(m) x 2(n) of 32x64 warp tiles.
// ---------------------------------------------------------------------------
#define GSTAGE 4
#define ASTR   36                      // floats per smem row (144B = 9x16B, conflict-free)
#define GSTB   (128 * ASTR * 4)        // stage bytes per operand
#define GEMM_SMEM_BYTES (2 * GSTAGE * GSTB)

__global__ __launch_bounds__(256) void gemm_cp(
    const float* __restrict__ A, const float* __restrict__ B,
    float* __restrict__ C, int M, int N, int K, int do_round)
{
    extern __shared__ float sm[];
    uint32_t as_u = smem_to_u32(sm);
    uint32_t bs_u = as_u + GSTAGE * GSTB;

    const int tid  = threadIdx.x;
    const int lane = tid & 31;
    const int w    = tid >> 5;
    const int wr   = w >> 1;      // 0..3 -> rows wr*32
    const int wc   = w & 1;       // 0..1 -> cols wc*64
    const int g    = lane >> 2;
    const int tig  = lane & 3;
    const int mrow = lane & 7;
    const int msel = lane >> 3;
    const int aro = (msel & 1) * 8 + mrow, aco = (msel >> 1) * 4;  // A-frag ldmatrix map
    const int bro = (msel >> 1) * 8 + mrow, bco = (msel & 1) * 4;  // B-frag ldmatrix map

    const int bm = blockIdx.y, bn = blockIdx.x;

    const float* Ag = A + (size_t)(bm * 128 + (tid >> 1)) * K + (tid & 1) * 16;
    const float* Bg = B + (size_t)(bn * 128 + (tid >> 1)) * K + (tid & 1) * 16;
    const uint32_t soff = ((tid >> 1) * ASTR + (tid & 1) * 16) * 4;

    auto issue = [&](int c) {
        const float* ap = Ag + c * 32;
        const float* bp = Bg + c * 32;
        uint32_t ad = as_u + (c & (GSTAGE - 1)) * GSTB + soff;
        uint32_t bd = bs_u + (c & (GSTAGE - 1)) * GSTB + soff;
        #pragma unroll
        for (int q = 0; q < 4; q++) {
            CP_ASYNC16(ad + q * 16, ap + q * 4);
            CP_ASYNC16(bd + q * 16, bp + q * 4);
        }
        CP_COMMIT;
    };

    float acc[2][8][4] = {};
    const int nch = K / 32;
    issue(0); issue(1); issue(2);

    for (int c = 0; c < nch; c++) {
        CP_WAIT_2;
        __syncthreads();
        if (c + 3 < nch) issue(c + 3);

        uint32_t ab = as_u + (c & (GSTAGE - 1)) * GSTB;
        uint32_t bb = bs_u + (c & (GSTAGE - 1)) * GSTB;
        #pragma unroll
        for (int ks = 0; ks < 4; ks++) {
            uint32_t af[2][4];
            #pragma unroll
            for (int mt = 0; mt < 2; mt++)
                LDSM_X4(af[mt][0], af[mt][1], af[mt][2], af[mt][3],
                        ab + (((wr * 32 + mt * 16 + aro) * ASTR) + ks * 8 + aco) * 4);
            uint32_t bf[8][2];
            #pragma unroll
            for (int nfp = 0; nfp < 4; nfp++)
                LDSM_X4(bf[2 * nfp][0], bf[2 * nfp][1], bf[2 * nfp + 1][0], bf[2 * nfp + 1][1],
                        bb + (((wc * 64 + nfp * 16 + bro) * ASTR) + ks * 8 + bco) * 4);
            #pragma unroll
            for (int mt = 0; mt < 2; mt++)
                #pragma unroll
                for (int nf = 0; nf < 8; nf++)
                    mma_tf32(acc[mt][nf], af[mt], bf[nf]);
        }
    }

    // epilogue
    #pragma unroll
    for (int mt = 0; mt < 2; mt++) {
        int row0 = bm * 128 + wr * 32 + mt * 16 + g;
        #pragma unroll
        for (int nf = 0; nf < 8; nf++) {
            int col = bn * 128 + wc * 64 + nf * 8 + 2 * tig;
            float v0 = acc[mt][nf][0], v1 = acc[mt][nf][1];
            float v2 = acc[mt][nf][2], v3 = acc[mt][nf][3];
            if (do_round) { v0 = f2tf_f(v0); v1 = f2tf_f(v1); v2 = f2tf_f(v2); v3 = f2tf_f(v3); }
            *(float2*)&C[(size_t)row0 * N + col]       = make_float2(v0, v1);
            *(float2*)&C[(size_t)(row0 + 8) * N + col] = make_float2(v2, v3);
        }
    }
}

// ---------------------------------------------------------------------------
// Causal flash attention, tf32 mma.sync + ldmatrix + register softmax.
// BQ=128, BKV=64, d=128. Grid (NH, T/128). 256 threads = 8 warps.
// S phase: warp tile 32x32; PV phase: warp tile 32x64.
// ---------------------------------------------------------------------------
#define BQ   128
#define BKV  64
#define QSTR 132   // 528B rows: 33x16B -> ldmatrix conflict-free, 16B aligned
#define VSTR 136   // V scalar-frag loads conflict-free (bank = 8tig+g)
#define SSTR 68    // 272B rows: 17x16B -> ldmatrix conflict-free

#define ATTN_SMEM_FLOATS (BQ*QSTR + BKV*QSTR + BKV*VSTR + BQ*SSTR + 2*256)
#define ATTN_SMEM_BYTES  (ATTN_SMEM_FLOATS * 4)

__global__ __launch_bounds__(256) void attn_kernel()
{
    extern __shared__ float sm[];
    float* Qs   = sm;                    // 128 x 132
    float* Ks   = Qs + BQ * QSTR;        // 64 x 132  [n][k]
    float* Vs   = Ks + BKV * QSTR;       // 64 x 136  [k][n]
    float* Ss   = Vs + BKV * VSTR;       // 128 x 68  P tile
    float* redm = Ss + BQ * SSTR;        // 128 x 2 max partials
    float* reds = redm + 256;            // 128 x 2 sum partials

    const int h   = blockIdx.x;
    const int qb  = (int)(gridDim.y - 1) - (int)blockIdx.y;  // heavy-first
    const int gkv = h >> 2;
    const int tid  = threadIdx.x;
    const int lane = tid & 31;
    const int w    = tid >> 5;
    const int wr   = w >> 1;     // 0..3
    const int wc   = w & 1;      // 0..1
    const int g    = lane >> 2;  // 0..7
    const int tig  = lane & 3;   // 0..3
    const int mrow = lane & 7;
    const int msel = lane >> 3;
    const int aro = (msel & 1) * 8 + mrow, aco = (msel >> 1) * 4;
    const int bro = (msel >> 1) * 8 + mrow, bco = (msel & 1) * 4;

    uint32_t qs_u = smem_to_u32(Qs);
    uint32_t ks_u = smem_to_u32(Ks);
    uint32_t vs_u = smem_to_u32(Vs);
    uint32_t ss_u = smem_to_u32(Ss);

    // Q tile (already scaled + tf32-rounded in global)
    for (int idx = tid; idx < BQ * 32; idx += 256) {
        int r = idx >> 5, c4 = (idx & 31) * 4;
        CP_ASYNC16(qs_u + (r * QSTR + c4) * 4,
                   &g_Q[(size_t)(qb * BQ + r) * D_MODEL + h * DH + c4]);
    }
    CP_COMMIT;

    float m_[2][2], l_[2][2];
    #pragma unroll
    for (int mt = 0; mt < 2; mt++) { m_[mt][0] = m_[mt][1] = -INFINITY; l_[mt][0] = l_[mt][1] = 0.f; }

    float o[2][8][4];
    #pragma unroll
    for (int mt = 0; mt < 2; mt++)
        #pragma unroll
        for (int nf = 0; nf < 8; nf++)
            #pragma unroll
            for (int i = 0; i < 4; i++) o[mt][nf][i] = 0.f;

    const int nkb = 2 * qb + 2;
    for (int kb = 0; kb < nkb; kb++) {
        __syncthreads();   // D: guard smem reuse from previous iteration
        for (int idx = tid; idx < BKV * 32; idx += 256) {
            int r = idx >> 5, c4 = (idx & 31) * 4;
            size_t goff = (size_t)(kb * BKV + r) * DKV + gkv * DH + c4;
            CP_ASYNC16(ks_u + (r * QSTR + c4) * 4, &g_K[goff]);
            CP_ASYNC16(vs_u + (r * VSTR + c4) * 4, &g_V[goff]);
        }
        CP_COMMIT;
        CP_WAIT_0;
        __syncthreads();   // A: tiles ready

        // ---- S = Q K^T ----
        float s[2][4][4];
        #pragma unroll
        for (int mt = 0; mt < 2; mt++)
            #pragma unroll
            for (int nf = 0; nf < 4; nf++)
                #pragma unroll
                for (int i = 0; i < 4; i++) s[mt][nf][i] = 0.f;

        #pragma unroll
        for (int ks = 0; ks < 16; ks++) {
            uint32_t af[2][4];
            #pragma unroll
            for (int mt = 0; mt < 2; mt++)
                LDSM_X4(af[mt][0], af[mt][1], af[mt][2], af[mt][3],
                        qs_u + (((wr * 32 + mt * 16 + aro) * QSTR) + ks * 8 + aco) * 4);
            uint32_t bf[4][2];
            #pragma unroll
            for (int nfp = 0; nfp < 2; nfp++)
                LDSM_X4(bf[2 * nfp][0], bf[2 * nfp][1], bf[2 * nfp + 1][0], bf[2 * nfp + 1][1],
                        ks_u + (((wc * 32 + nfp * 16 + bro) * QSTR) + ks * 8 + bco) * 4);
            #pragma unroll
            for (int mt = 0; mt < 2; mt++)
                #pragma unroll
                for (int nf = 0; nf < 4; nf++)
                    mma_tf32(s[mt][nf], af[mt], bf[nf]);
        }

        // causal mask on diagonal-overlapping blocks
        if (kb >= 2 * qb) {
            #pragma unroll
            for (int mt = 0; mt < 2; mt++) {
                int row0 = qb * BQ + wr * 32 + mt * 16 + g;
                #pragma unroll
                for (int nf = 0; nf < 4; nf++) {
                    int col = kb * BKV + wc * 32 + nf * 8 + 2 * tig;
                    if (col > row0)         s[mt][nf][0] = -INFINITY;
                    if (col + 1 > row0)     s[mt][nf][1] = -INFINITY;
                    if (col > row0 + 8)     s[mt][nf][2] = -INFINITY;
                    if (col + 1 > row0 + 8) s[mt][nf][3] = -INFINITY;
                }
            }
        }

        // ---- register softmax: row max ----
        float pm[2][2];
        #pragma unroll
        for (int mt = 0; mt < 2; mt++) {
            float a0 = -INFINITY, a1 = -INFINITY;
            #pragma unroll
            for (int nf = 0; nf < 4; nf++) {
                a0 = fmaxf(a0, fmaxf(s[mt][nf][0], s[mt][nf][1]));
                a1 = fmaxf(a1, fmaxf(s[mt][nf][2], s[mt][nf][3]));
            }
            a0 = fmaxf(a0, __shfl_xor_sync(0xffffffffu, a0, 1));
            a0 = fmaxf(a0, __shfl_xor_sync(0xffffffffu, a0, 2));
            a1 = fmaxf(a1, __shfl_xor_sync(0xffffffffu, a1, 1));
            a1 = fmaxf(a1, __shfl_xor_sync(0xffffffffu, a1, 2));
            pm[mt][0] = a0; pm[mt][1] = a1;
        }
        if (tig == 0) {
            #pragma unroll
            for (int mt = 0; mt < 2; mt++) {
                int r0 = wr * 32 + mt * 16 + g;
                redm[r0 * 2 + wc]       = pm[mt][0];
                redm[(r0 + 8) * 2 + wc] = pm[mt][1];
            }
        }
        __syncthreads();   // B: max partials visible

        float alpha[2][2];
        #pragma unroll
        for (int mt = 0; mt < 2; mt++)
            #pragma unroll
            for (int i = 0; i < 2; i++) {
                int r = wr * 32 + mt * 16 + g + i * 8;
                float mb = fmaxf(redm[r * 2], redm[r * 2 + 1]);
                float mn = fmaxf(m_[mt][i], mb);
                alpha[mt][i] = __expf(m_[mt][i] - mn);
                m_[mt][i] = mn;
            }

        // ---- exp (tf32-rounded P), partial sums, write P to smem ----
        float psum[2][2] = {};
        #pragma unroll
        for (int mt = 0; mt < 2; mt++) {
            int r0 = wr * 32 + mt * 16 + g;
            #pragma unroll
            for (int nf = 0; nf < 4; nf++) {
                float p0 = f2tf_f(__expf(s[mt][nf][0] - m_[mt][0]));
                float p1 = f2tf_f(__expf(s[mt][nf][1] - m_[mt][0]));
                float p2 = f2tf_f(__expf(s[mt][nf][2] - m_[mt][1]));
                float p3 = f2tf_f(__expf(s[mt][nf][3] - m_[mt][1]));
                psum[mt][0] += p0 + p1;
                psum[mt][1] += p2 + p3;
                int c0 = wc * 32 + nf * 8 + 2 * tig;
                *(float2*)&Ss[r0 * SSTR + c0]       = make_float2(p0, p1);
                *(float2*)&Ss[(r0 + 8) * SSTR + c0] = make_float2(p2, p3);
            }
            psum[mt][0] += __shfl_xor_sync(0xffffffffu, psum[mt][0], 1);
            psum[mt][0] += __shfl_xor_sync(0xffffffffu, psum[mt][0], 2);
            psum[mt][1] += __shfl_xor_sync(0xffffffffu, psum[mt][1], 1);
            psum[mt][1] += __shfl_xor_sync(0xffffffffu, psum[mt][1], 2);
        }
        if (tig == 0) {
            #pragma unroll
            for (int mt = 0; mt < 2; mt++) {
                int r0 = wr * 32 + mt * 16 + g;
                reds[r0 * 2 + wc]       = psum[mt][0];
                reds[(r0 + 8) * 2 + wc] = psum[mt][1];
            }
        }
        __syncthreads();   // C: P tile + sum partials visible

        #pragma unroll
        for (int mt = 0; mt < 2; mt++)
            #pragma unroll
            for (int i = 0; i < 2; i++) {
                int r = wr * 32 + mt * 16 + g + i * 8;
                l_[mt][i] = l_[mt][i] * alpha[mt][i] + (reds[r * 2] + reds[r * 2 + 1]);
            }

        // rescale O
        #pragma unroll
        for (int mt = 0; mt < 2; mt++)
            #pragma unroll
            for (int nf = 0; nf < 8; nf++) {
                o[mt][nf][0] *= alpha[mt][0]; o[mt][nf][1] *= alpha[mt][0];
                o[mt][nf][2] *= alpha[mt][1]; o[mt][nf][3] *= alpha[mt][1];
            }

        // ---- O += P @ V ----
        #pragma unroll
        for (int ks = 0; ks < 8; ks++) {
            uint32_t af[2][4];
            #pragma unroll
            for (int mt = 0; mt < 2; mt++)
                LDSM_X4(af[mt][0], af[mt][1], af[mt][2], af[mt][3],
                        ss_u + (((wr * 32 + mt * 16 + aro) * SSTR) + ks * 8 + aco) * 4);
            uint32_t bf[8][2];
            #pragma unroll
            for (int nf = 0; nf < 8; nf++) {
                int c0 = wc * 64 + nf * 8 + g;
                bf[nf][0] = fu(Vs[(ks * 8 + tig) * VSTR + c0]);
                bf[nf][1] = fu(Vs[(ks * 8 + tig + 4) * VSTR + c0]);
            }
            #pragma unroll
            for (int mt = 0; mt < 2; mt++)
                #pragma unroll
                for (int nf = 0; nf < 8; nf++)
                    mma_tf32(o[mt][nf], af[mt], bf[nf]);
        }
    }

    // epilogue (tf32-rounded for the WO gemm)
    #pragma unroll
    for (int mt = 0; mt < 2; mt++) {
        int r0 = wr * 32 + mt * 16 + g;
        float inv0 = 1.f / l_[mt][0];
        float inv1 = 1.f / l_[mt][1];
        int trow0 = qb * BQ + r0;
        #pragma unroll
        for (int nf = 0; nf < 8; nf++) {
            int col = h * DH + wc * 64 + nf * 8 + 2 * tig;
            *(float2*)&g_Ctx[(size_t)trow0 * D_MODEL + col] =
                make_float2(f2tf_f(o[mt][nf][0] * inv0), f2tf_f(o[mt][nf][1] * inv0));
            *(float2*)&g_Ctx[(size_t)(trow0 + 8) * D_MODEL + col] =
                make_float2(f2tf_f(o[mt][nf][2] * inv1), f2tf_f(o[mt][nf][3] * inv1));
        }
    }
}

// ---------------------------------------------------------------------------
extern "C" void kernel_launch(void* const* d_in, const int* in_sizes, int n_in,
                              void* d_out, int out_size)
{
    const float* x  = (const float*)d_in[0];
    const float* WQ = (const float*)d_in[1];
    const float* WK = (const float*)d_in[2];
    const float* WV = (const float*)d_in[3];
    const float* WO = (const float*)d_in[4];
    float* out = (float*)d_out;

    float *Qp, *Kp, *Vp, *Cp, *xTp, *wtq, *wtk, *wtv, *wto;
    cudaGetSymbolAddress((void**)&Qp, g_Q);
    cudaGetSymbolAddress((void**)&Kp, g_K);
    cudaGetSymbolAddress((void**)&Vp, g_V);
    cudaGetSymbolAddress((void**)&Cp, g_Ctx);
    cudaGetSymbolAddress((void**)&xTp, g_xT);
    cudaGetSymbolAddress((void**)&wtq, g_WTq);
    cudaGetSymbolAddress((void**)&wtk, g_WTk);
    cudaGetSymbolAddress((void**)&wtv, g_WTv);
    cudaGetSymbolAddress((void**)&wto, g_WTo);

    cudaFuncSetAttribute(gemm_cp, cudaFuncAttributeMaxDynamicSharedMemorySize,
                         GEMM_SMEM_BYTES);
    cudaFuncSetAttribute(attn_kernel, cudaFuncAttributeMaxDynamicSharedMemorySize,
                         ATTN_SMEM_BYTES);

    const float scale = 0.08838834764831845f;  // 1/sqrt(128)

    // prep: tf32-round x, transpose+round weights, rope tables
    round_x<<<(T_SEQ * D_MODEL / 4 + 255) / 256, 256>>>(x);
    transpose_w<<<dim3(D_MODEL / 32, D_MODEL / 32, 4), dim3(32, 8)>>>(WQ, WK, WV, WO);
    {
        int n = T_SEQ * (DH / 2);
        rope_table<<<(n + 255) / 256, 256>>>();
    }

    // projections
    gemm_cp<<<dim3(D_MODEL / 128, T_SEQ / 128), 256, GEMM_SMEM_BYTES>>>(
        xTp, wtq, Qp, T_SEQ, D_MODEL, D_MODEL, 0);
    gemm_cp<<<dim3(DKV / 128, T_SEQ / 128), 256, GEMM_SMEM_BYTES>>>(
        xTp, wtk, Kp, T_SEQ, DKV, D_MODEL, 0);
    gemm_cp<<<dim3(DKV / 128, T_SEQ / 128), 256, GEMM_SMEM_BYTES>>>(
        xTp, wtv, Vp, T_SEQ, DKV, D_MODEL, 1);

    // rope (Q also folds softmax scale; both round to tf32)
    {
        int n = T_SEQ * (D_MODEL / 2);
        rope_apply<<<(n + 255) / 256, 256>>>(Qp, D_MODEL, scale);
    }
    {
        int n = T_SEQ * (DKV / 2);
        rope_apply<<<(n + 255) / 256, 256>>>(Kp, DKV, 1.0f);
    }

    // attention
    attn_kernel<<<dim3(NH, T_SEQ / BQ), 256, ATTN_SMEM_BYTES>>>();

    // output projection
    gemm_cp<<<dim3(D_MODEL / 128, T_SEQ / 128), 256, GEMM_SMEM_BYTES>>>(
        Cp, wto, out, T_SEQ, D_MODEL, D_MODEL, 0);
}